// round 14
// baseline (speedup 1.0000x reference)
#include <cuda_runtime.h>
#include <cuda_bf16.h>

#define W    1280
#define W4   320               // row width in float4
#define H    384
#define NB   8
#define ROWS 4                 // output rows per thread
#define NLOAD (ROWS + 2)       // input rows needed
#define NT   512
#define GROUPS (H / ROWS)      // 96 row-groups
// total threads = NB * GROUPS * W4 = 245760 = 480 blocks * 512
// R13 schedule exactly (front-batched float4 + float2 per row); only the
// block granularity changes (512 threads -> 480 blocks). Batch boundaries
// align to block boundaries (60 blocks per batch), so bsline stays
// block-uniform.

// Separable form: mask(x) = min(1, 1 + sum_{3 rows} g(r,x)),
//   g(r,x) = (d(r,x)+d(r,x+-1))/6 - d(r,x+-2)/3   (sign from bsline)
// (disp in [0,1] => taps i>=1 of the reference's 21-tap min exceed the clip
// ceiling 1 and tap 0 is positive, so min+clip collapses to tap 0.)
__global__ void __launch_bounds__(NT)
self_occlu_mask_kernel(const float* __restrict__ D,
                       const float* __restrict__ bs,
                       float* __restrict__ out)
{
    const int tid  = blockIdx.x * NT + threadIdx.x;
    const int p    = tid % W4;                // float4 column
    const int rest = tid / W4;
    const int g    = rest % GROUPS;           // row group
    const int n    = rest / GROUPS;           // batch (uniform per block)
    const int h0   = g * ROWS;

    const long long plane4 = (long long)H * W4;
    float4* O = (float4*)out + (long long)n * plane4 + (long long)h0 * W4;

    const float b = __ldg(&bs[n]);            // uniform per block
    if (b == 0.0f) {
        const float4 z = make_float4(0.f, 0.f, 0.f, 0.f);
        #pragma unroll
        for (int j = 0; j < ROWS; j++) O[j * W4 + p] = z;
        return;
    }

    const float4* Dn = (const float4*)D + (long long)n * plane4;
    const bool right = (b > 0.0f);

    // Far-side columns: only 2 floats needed -> float2 load (8B aligned).
    //  left  mask needs w4,w5 = row[p+1].xy ; right mask needs w2,w3 = row[p-1].zw
    const int pf   = right ? max(p - 1, 0) : min(p + 1, W4 - 1);
    const int foff = right ? 2 : 0;

    // Front-batched independent loads: 1 float4 + 1 float2 per input row.
    float4 v[NLOAD];
    float2 e[NLOAD];
    #pragma unroll
    for (int k = 0; k < NLOAD; k++) {
        const int rk = min(max(h0 - 1 + k, 0), H - 1);
        const float4* row = Dn + (long long)rk * W4;
        v[k] = row[p];
        e[k] = *(const float2*)((const float*)row + 4 * pf + foff);
    }

    const float inv6 = 1.0f / 6.0f;
    const float mth  = -(1.0f / 3.0f);

    // Horizontal taps per input row.
    float4 gg[NLOAD];
    if (right) {
        #pragma unroll
        for (int k = 0; k < NLOAD; k++) {
            const float w4 = v[k].x, w5 = v[k].y, w6 = v[k].z, w7 = v[k].w;
            float w2 = e[k].x, w3 = e[k].y;
            if (p == 0) { w2 = w4; w3 = w4; }        // edge replicate
            gg[k].x = fmaf(w2, mth, (w4 + w3) * inv6);
            gg[k].y = fmaf(w3, mth, (w5 + w4) * inv6);
            gg[k].z = fmaf(w4, mth, (w6 + w5) * inv6);
            gg[k].w = fmaf(w5, mth, (w7 + w6) * inv6);
        }
    } else {
        #pragma unroll
        for (int k = 0; k < NLOAD; k++) {
            const float w0 = v[k].x, w1 = v[k].y, w2 = v[k].z, w3 = v[k].w;
            float w4 = e[k].x, w5 = e[k].y;
            if (p == W4 - 1) { w4 = w3; w5 = w3; }   // edge replicate
            gg[k].x = fmaf(w2, mth, (w0 + w1) * inv6);
            gg[k].y = fmaf(w3, mth, (w1 + w2) * inv6);
            gg[k].z = fmaf(w4, mth, (w2 + w3) * inv6);
            gg[k].w = fmaf(w5, mth, (w3 + w4) * inv6);
        }
    }

    // Vertical 3-sum + clip, store.
    #pragma unroll
    for (int j = 0; j < ROWS; j++) {
        float4 r;
        r.x = fminf(1.0f + gg[j].x + gg[j + 1].x + gg[j + 2].x, 1.0f);
        r.y = fminf(1.0f + gg[j].y + gg[j + 1].y + gg[j + 2].y, 1.0f);
        r.z = fminf(1.0f + gg[j].z + gg[j + 1].z + gg[j + 2].z, 1.0f);
        r.w = fminf(1.0f + gg[j].w + gg[j + 1].w + gg[j + 2].w, 1.0f);
        O[j * W4 + p] = r;
    }
}

extern "C" void kernel_launch(void* const* d_in, const int* in_sizes, int n_in,
                              void* d_out, int out_size)
{
    const float* dispmap = (const float*)d_in[0];   // (8,1,384,1280) f32
    const float* bsline  = (const float*)d_in[1];   // (8,) f32
    float*       out     = (float*)d_out;

    const int blocks = NB * GROUPS * W4 / NT;       // 480
    self_occlu_mask_kernel<<<blocks, NT>>>(dispmap, bsline, out);
}

// round 15
// speedup vs baseline: 2.4539x; 2.4539x over previous
#include <cuda_runtime.h>
#include <cuda_bf16.h>

#define W    1280
#define W4   320               // row width in float4
#define H    384
#define NB   8
#define ROWS 4                 // output rows per thread
#define NLOAD (ROWS + 2)       // input rows needed
#define NT   256
#define GROUPS (H / ROWS)      // 96 row-groups
// total threads = NB * GROUPS * W4 = 245760 = 960 blocks * 256
// Empirical optimum (R13): front-batched float4 + float2 loads per row,
// ROWS=4, NT=256, unconstrained regs (46 -> 5 blocks/SM).

// Separable form: mask(x) = min(1, 1 + sum_{3 rows} g(r,x)),
//   g(r,x) = (d(r,x)+d(r,x+-1))/6 - d(r,x+-2)/3   (sign from bsline)
// (disp in [0,1] => taps i>=1 of the reference's 21-tap min exceed the clip
// ceiling 1 and tap 0 is positive, so min+clip collapses to tap 0.)
__global__ void __launch_bounds__(NT)
self_occlu_mask_kernel(const float* __restrict__ D,
                       const float* __restrict__ bs,
                       float* __restrict__ out)
{
    const int tid  = blockIdx.x * NT + threadIdx.x;
    const int p    = tid % W4;                // float4 column
    const int rest = tid / W4;
    const int g    = rest % GROUPS;           // row group
    const int n    = rest / GROUPS;           // batch (uniform per block)
    const int h0   = g * ROWS;

    const long long plane4 = (long long)H * W4;
    float4* O = (float4*)out + (long long)n * plane4 + (long long)h0 * W4;

    const float b = __ldg(&bs[n]);            // uniform per block
    if (b == 0.0f) {
        const float4 z = make_float4(0.f, 0.f, 0.f, 0.f);
        #pragma unroll
        for (int j = 0; j < ROWS; j++) O[j * W4 + p] = z;
        return;
    }

    const float4* Dn = (const float4*)D + (long long)n * plane4;
    const bool right = (b > 0.0f);

    // Far-side columns: only 2 floats needed -> float2 load (8B aligned).
    //  left  mask needs w4,w5 = row[p+1].xy ; right mask needs w2,w3 = row[p-1].zw
    const int pf   = right ? max(p - 1, 0) : min(p + 1, W4 - 1);
    const int foff = right ? 2 : 0;

    // Front-batched independent loads: 1 float4 + 1 float2 per input row.
    float4 v[NLOAD];
    float2 e[NLOAD];
    #pragma unroll
    for (int k = 0; k < NLOAD; k++) {
        const int rk = min(max(h0 - 1 + k, 0), H - 1);
        const float4* row = Dn + (long long)rk * W4;
        v[k] = row[p];
        e[k] = *(const float2*)((const float*)row + 4 * pf + foff);
    }

    const float inv6 = 1.0f / 6.0f;
    const float mth  = -(1.0f / 3.0f);

    // Horizontal taps per input row.
    float4 gg[NLOAD];
    if (right) {
        #pragma unroll
        for (int k = 0; k < NLOAD; k++) {
            const float w4 = v[k].x, w5 = v[k].y, w6 = v[k].z, w7 = v[k].w;
            float w2 = e[k].x, w3 = e[k].y;
            if (p == 0) { w2 = w4; w3 = w4; }        // edge replicate
            gg[k].x = fmaf(w2, mth, (w4 + w3) * inv6);
            gg[k].y = fmaf(w3, mth, (w5 + w4) * inv6);
            gg[k].z = fmaf(w4, mth, (w6 + w5) * inv6);
            gg[k].w = fmaf(w5, mth, (w7 + w6) * inv6);
        }
    } else {
        #pragma unroll
        for (int k = 0; k < NLOAD; k++) {
            const float w0 = v[k].x, w1 = v[k].y, w2 = v[k].z, w3 = v[k].w;
            float w4 = e[k].x, w5 = e[k].y;
            if (p == W4 - 1) { w4 = w3; w5 = w3; }   // edge replicate
            gg[k].x = fmaf(w2, mth, (w0 + w1) * inv6);
            gg[k].y = fmaf(w3, mth, (w1 + w2) * inv6);
            gg[k].z = fmaf(w4, mth, (w2 + w3) * inv6);
            gg[k].w = fmaf(w5, mth, (w3 + w4) * inv6);
        }
    }

    // Vertical 3-sum + clip, store.
    #pragma unroll
    for (int j = 0; j < ROWS; j++) {
        float4 r;
        r.x = fminf(1.0f + gg[j].x + gg[j + 1].x + gg[j + 2].x, 1.0f);
        r.y = fminf(1.0f + gg[j].y + gg[j + 1].y + gg[j + 2].y, 1.0f);
        r.z = fminf(1.0f + gg[j].z + gg[j + 1].z + gg[j + 2].z, 1.0f);
        r.w = fminf(1.0f + gg[j].w + gg[j + 1].w + gg[j + 2].w, 1.0f);
        O[j * W4 + p] = r;
    }
}

extern "C" void kernel_launch(void* const* d_in, const int* in_sizes, int n_in,
                              void* d_out, int out_size)
{
    const float* dispmap = (const float*)d_in[0];   // (8,1,384,1280) f32
    const float* bsline  = (const float*)d_in[1];   // (8,) f32
    float*       out     = (float*)d_out;

    const int blocks = NB * GROUPS * W4 / NT;       // 960
    self_occlu_mask_kernel<<<blocks, NT>>>(dispmap, bsline, out);
}

// round 16
// speedup vs baseline: 2.4630x; 1.0037x over previous
#include <cuda_runtime.h>
#include <cuda_bf16.h>

#define W    1280
#define W4   320               // row width in float4
#define H    384
#define NB   8
#define ROWS 4                 // output rows per thread
#define NLOAD (ROWS + 2)       // input rows needed
#define NT   256
#define GROUPS (H / ROWS)      // 96 row-groups
// total threads = NB * GROUPS * W4 = 245760 = 960 blocks * 256
// Converged optimum (R13): front-batched float4 + float2 loads per row,
// ROWS=4, NT=256, unconstrained regs (46 -> 5 blocks/SM).

// Separable form: mask(x) = min(1, 1 + sum_{3 rows} g(r,x)),
//   g(r,x) = (d(r,x)+d(r,x+-1))/6 - d(r,x+-2)/3   (sign from bsline)
// (disp in [0,1] => taps i>=1 of the reference's 21-tap min exceed the clip
// ceiling 1 and tap 0 is positive, so min+clip collapses to tap 0.)
__global__ void __launch_bounds__(NT)
self_occlu_mask_kernel(const float* __restrict__ D,
                       const float* __restrict__ bs,
                       float* __restrict__ out)
{
    const int tid  = blockIdx.x * NT + threadIdx.x;
    const int p    = tid % W4;                // float4 column
    const int rest = tid / W4;
    const int g    = rest % GROUPS;           // row group
    const int n    = rest / GROUPS;           // batch (uniform per block)
    const int h0   = g * ROWS;

    const long long plane4 = (long long)H * W4;
    float4* O = (float4*)out + (long long)n * plane4 + (long long)h0 * W4;

    const float b = __ldg(&bs[n]);            // uniform per block
    if (b == 0.0f) {
        const float4 z = make_float4(0.f, 0.f, 0.f, 0.f);
        #pragma unroll
        for (int j = 0; j < ROWS; j++) O[j * W4 + p] = z;
        return;
    }

    const float4* Dn = (const float4*)D + (long long)n * plane4;
    const bool right = (b > 0.0f);

    // Far-side columns: only 2 floats needed -> float2 load (8B aligned).
    //  left  mask needs w4,w5 = row[p+1].xy ; right mask needs w2,w3 = row[p-1].zw
    const int pf   = right ? max(p - 1, 0) : min(p + 1, W4 - 1);
    const int foff = right ? 2 : 0;

    // Front-batched independent loads: 1 float4 + 1 float2 per input row.
    float4 v[NLOAD];
    float2 e[NLOAD];
    #pragma unroll
    for (int k = 0; k < NLOAD; k++) {
        const int rk = min(max(h0 - 1 + k, 0), H - 1);
        const float4* row = Dn + (long long)rk * W4;
        v[k] = row[p];
        e[k] = *(const float2*)((const float*)row + 4 * pf + foff);
    }

    const float inv6 = 1.0f / 6.0f;
    const float mth  = -(1.0f / 3.0f);

    // Horizontal taps per input row.
    float4 gg[NLOAD];
    if (right) {
        #pragma unroll
        for (int k = 0; k < NLOAD; k++) {
            const float w4 = v[k].x, w5 = v[k].y, w6 = v[k].z, w7 = v[k].w;
            float w2 = e[k].x, w3 = e[k].y;
            if (p == 0) { w2 = w4; w3 = w4; }        // edge replicate
            gg[k].x = fmaf(w2, mth, (w4 + w3) * inv6);
            gg[k].y = fmaf(w3, mth, (w5 + w4) * inv6);
            gg[k].z = fmaf(w4, mth, (w6 + w5) * inv6);
            gg[k].w = fmaf(w5, mth, (w7 + w6) * inv6);
        }
    } else {
        #pragma unroll
        for (int k = 0; k < NLOAD; k++) {
            const float w0 = v[k].x, w1 = v[k].y, w2 = v[k].z, w3 = v[k].w;
            float w4 = e[k].x, w5 = e[k].y;
            if (p == W4 - 1) { w4 = w3; w5 = w3; }   // edge replicate
            gg[k].x = fmaf(w2, mth, (w0 + w1) * inv6);
            gg[k].y = fmaf(w3, mth, (w1 + w2) * inv6);
            gg[k].z = fmaf(w4, mth, (w2 + w3) * inv6);
            gg[k].w = fmaf(w5, mth, (w3 + w4) * inv6);
        }
    }

    // Vertical 3-sum + clip, store.
    #pragma unroll
    for (int j = 0; j < ROWS; j++) {
        float4 r;
        r.x = fminf(1.0f + gg[j].x + gg[j + 1].x + gg[j + 2].x, 1.0f);
        r.y = fminf(1.0f + gg[j].y + gg[j + 1].y + gg[j + 2].y, 1.0f);
        r.z = fminf(1.0f + gg[j].z + gg[j + 1].z + gg[j + 2].z, 1.0f);
        r.w = fminf(1.0f + gg[j].w + gg[j + 1].w + gg[j + 2].w, 1.0f);
        O[j * W4 + p] = r;
    }
}

extern "C" void kernel_launch(void* const* d_in, const int* in_sizes, int n_in,
                              void* d_out, int out_size)
{
    const float* dispmap = (const float*)d_in[0];   // (8,1,384,1280) f32
    const float* bsline  = (const float*)d_in[1];   // (8,) f32
    float*       out     = (float*)d_out;

    const int blocks = NB * GROUPS * W4 / NT;       // 960
    self_occlu_mask_kernel<<<blocks, NT>>>(dispmap, bsline, out);
}